// round 1
// baseline (speedup 1.0000x reference)
#include <cuda_runtime.h>
#include <cub/cub.cuh>

// Problem constants (fixed by the reference setup_inputs)
constexpr int B  = 64;
constexpr int H  = 512;
constexpr int W  = 512;
constexpr int HW = H * W;        // 262144 = 2^18
constexpr int N  = B * HW;       // 16777216

// Static scratch (no allocation allowed): double buffer for 64-bit keys + cub temp
__device__ unsigned long long g_keys_a[N];
__device__ unsigned long long g_keys_b[N];
__device__ unsigned char      g_temp[64 << 20];

// ---------------------------------------------------------------------------
// Kernel 1: 8-neighbor NMS (original-value comparisons) + composite key encode
// key = (batch << 50) | (descending-ordered score bits << 18) | local_idx
// Ascending radix sort of these keys == stable argsort(-flat) per batch.
// ---------------------------------------------------------------------------
__global__ void nms_encode_kernel(const float* __restrict__ hm,
                                  unsigned long long* __restrict__ keys) {
    int g = blockIdx.x * blockDim.x + threadIdx.x;
    if (g >= N) return;
    int idx = g & (HW - 1);
    int b   = g >> 18;
    int y   = idx >> 9;
    int x   = idx & (W - 1);

    const float* img = hm + (size_t)b * HW;
    float v = __ldg(img + idx);

    float m = -__int_as_float(0x7f800000);  // -inf
    if (y > 0) {
        const float* r = img + (y - 1) * W + x;
        if (x > 0)      m = fmaxf(m, __ldg(r - 1));
        m = fmaxf(m, __ldg(r));
        if (x < W - 1)  m = fmaxf(m, __ldg(r + 1));
    }
    {
        const float* r = img + y * W + x;
        if (x > 0)      m = fmaxf(m, __ldg(r - 1));
        if (x < W - 1)  m = fmaxf(m, __ldg(r + 1));
    }
    if (y < H - 1) {
        const float* r = img + (y + 1) * W + x;
        if (x > 0)      m = fmaxf(m, __ldg(r - 1));
        m = fmaxf(m, __ldg(r));
        if (x < W - 1)  m = fmaxf(m, __ldg(r + 1));
    }

    float jv = (m >= v) ? 0.6f * v : v;

    // float -> ascending-ordered uint, then invert for descending order
    unsigned u = __float_as_uint(jv);
    unsigned e = u ^ (((unsigned)((int)u >> 31)) | 0x80000000u);
    unsigned d = ~e;

    keys[g] = ((unsigned long long)(unsigned)b << 50)
            | ((unsigned long long)d << 18)
            | (unsigned long long)(unsigned)idx;
}

// ---------------------------------------------------------------------------
// Kernel 2: decode sorted keys -> (y + yo + 0.5, x + xo + 0.5, score)
// Score recovered exactly from the key bits (no gather of the NMS map).
// ---------------------------------------------------------------------------
__global__ void decode_kernel(const unsigned long long* __restrict__ keys,
                              const float* __restrict__ off,
                              float* __restrict__ out) {
    int g = blockIdx.x * blockDim.x + threadIdx.x;
    if (g >= N) return;

    unsigned long long k = keys[g];
    int idx    = (int)(k & 0x3FFFFull);
    unsigned d = (unsigned)(k >> 18);   // low 32 of the shifted field
    unsigned e = ~d;
    unsigned mask = (e & 0x80000000u) ? 0x80000000u : 0xFFFFFFFFu;
    float score = __uint_as_float(e ^ mask);

    int b = g >> 18;
    int y = idx >> 9;
    int x = idx & (W - 1);

    const float* ob = off + (size_t)b * 2 * HW;
    float xo = __ldg(ob + idx);        // channel 0: x-offset
    float yo = __ldg(ob + HW + idx);   // channel 1: y-offset

    float* o = out + (size_t)g * 3;
    o[0] = (float)y + yo + 0.5f;
    o[1] = (float)x + xo + 0.5f;
    o[2] = score;
}

extern "C" void kernel_launch(void* const* d_in, const int* in_sizes, int n_in,
                              void* d_out, int out_size) {
    const float* hm  = (const float*)d_in[0];
    const float* off = (const float*)d_in[1];
    float* out = (float*)d_out;

    unsigned long long* ka = nullptr;
    unsigned long long* kb = nullptr;
    void* tmp = nullptr;
    cudaGetSymbolAddress((void**)&ka, g_keys_a);
    cudaGetSymbolAddress((void**)&kb, g_keys_b);
    cudaGetSymbolAddress(&tmp, g_temp);

    const int threads = 256;
    const int blocks  = (N + threads - 1) / threads;

    nms_encode_kernel<<<blocks, threads>>>(hm, ka);

    cub::DoubleBuffer<unsigned long long> dkeys(ka, kb);
    size_t temp_bytes = sizeof(g_temp);
    cub::DeviceRadixSort::SortKeys(tmp, temp_bytes, dkeys, N,
                                   /*begin_bit=*/0, /*end_bit=*/56,
                                   /*stream=*/0);

    decode_kernel<<<blocks, threads>>>(dkeys.Current(), off, out);
}

// round 2
// speedup vs baseline: 1.3587x; 1.3587x over previous
#include <cuda_runtime.h>
#include <cub/cub.cuh>

// Problem constants (fixed by the reference setup_inputs)
constexpr int B  = 64;
constexpr int H  = 512;
constexpr int W  = 512;
constexpr int HW = H * W;        // 262144 = 2^18
constexpr int N  = B * HW;       // 16777216

// Static scratch (no allocation allowed):
//   double buffers for 32-bit keys + 32-bit values, plus cub temp
__device__ unsigned g_keys_a[N];
__device__ unsigned g_keys_b[N];
__device__ unsigned g_vals_a[N];
__device__ unsigned g_vals_b[N];
__device__ unsigned char g_temp[64 << 20];

// ---------------------------------------------------------------------------
// Kernel 1: 8-neighbor NMS (comparisons on ORIGINAL values) + key encode.
//   keys[g] = descending-ordered bit mapping of suppressed score
//   vals[g] = g   (global index: (b<<18) | idx — identity iota)
// Stable ascending radix sort of (keys, vals) == stable argsort(-score).
// ---------------------------------------------------------------------------
__global__ void nms_encode_kernel(const float* __restrict__ hm,
                                  unsigned* __restrict__ keys,
                                  unsigned* __restrict__ vals) {
    int g = blockIdx.x * blockDim.x + threadIdx.x;
    if (g >= N) return;
    int idx = g & (HW - 1);
    int b   = g >> 18;
    int y   = idx >> 9;
    int x   = idx & (W - 1);

    const float* img = hm + (size_t)b * HW;
    float v = __ldg(img + idx);

    float m = -__int_as_float(0x7f800000);  // -inf
    if (y > 0) {
        const float* r = img + (y - 1) * W + x;
        if (x > 0)      m = fmaxf(m, __ldg(r - 1));
        m = fmaxf(m, __ldg(r));
        if (x < W - 1)  m = fmaxf(m, __ldg(r + 1));
    }
    {
        const float* r = img + y * W + x;
        if (x > 0)      m = fmaxf(m, __ldg(r - 1));
        if (x < W - 1)  m = fmaxf(m, __ldg(r + 1));
    }
    if (y < H - 1) {
        const float* r = img + (y + 1) * W + x;
        if (x > 0)      m = fmaxf(m, __ldg(r - 1));
        m = fmaxf(m, __ldg(r));
        if (x < W - 1)  m = fmaxf(m, __ldg(r + 1));
    }

    float jv = (m >= v) ? 0.6f * v : v;

    // float -> ascending-ordered uint, then invert for descending order
    unsigned u = __float_as_uint(jv);
    unsigned e = u ^ (((unsigned)((int)u >> 31)) | 0x80000000u);
    keys[g] = ~e;
    vals[g] = (unsigned)g;
}

// ---------------------------------------------------------------------------
// Kernel 2: decode (v, d) pairs (batch-partitioned, score-sorted) ->
//           (y + yo + 0.5, x + xo + 0.5, score)
// Output position g is already final; offsets gathered batch-locally
// (2 MB/batch planes -> L2 resident).
// ---------------------------------------------------------------------------
__global__ void decode_kernel(const unsigned* __restrict__ vsorted,
                              const unsigned* __restrict__ dsorted,
                              const float* __restrict__ off,
                              float* __restrict__ out) {
    int g = blockIdx.x * blockDim.x + threadIdx.x;
    if (g >= N) return;

    unsigned v = vsorted[g];
    unsigned d = dsorted[g];

    int idx = (int)(v & 0x3FFFFu);
    int b   = (int)(v >> 18);
    int y   = idx >> 9;
    int x   = idx & (W - 1);

    unsigned e = ~d;
    unsigned mask = (e & 0x80000000u) ? 0x80000000u : 0xFFFFFFFFu;
    float score = __uint_as_float(e ^ mask);

    const float* ob = off + (size_t)b * 2 * HW;
    float xo = __ldg(ob + idx);        // channel 0: x-offset
    float yo = __ldg(ob + HW + idx);   // channel 1: y-offset

    float* o = out + (size_t)g * 3;
    o[0] = (float)y + yo + 0.5f;
    o[1] = (float)x + xo + 0.5f;
    o[2] = score;
}

extern "C" void kernel_launch(void* const* d_in, const int* in_sizes, int n_in,
                              void* d_out, int out_size) {
    const float* hm  = (const float*)d_in[0];
    const float* off = (const float*)d_in[1];
    float* out = (float*)d_out;

    unsigned *ka = nullptr, *kb = nullptr, *va = nullptr, *vb = nullptr;
    void* tmp = nullptr;
    cudaGetSymbolAddress((void**)&ka, g_keys_a);
    cudaGetSymbolAddress((void**)&kb, g_keys_b);
    cudaGetSymbolAddress((void**)&va, g_vals_a);
    cudaGetSymbolAddress((void**)&vb, g_vals_b);
    cudaGetSymbolAddress(&tmp, g_temp);

    const int threads = 256;
    const int blocks  = (N + threads - 1) / threads;

    nms_encode_kernel<<<blocks, threads>>>(hm, ka, va);

    // Phase 1: stable sort by full 32-bit descending-mapped score (4 passes).
    cub::DoubleBuffer<unsigned> dkeys(ka, kb);
    cub::DoubleBuffer<unsigned> dvals(va, vb);
    size_t temp_bytes = sizeof(g_temp);
    cub::DeviceRadixSort::SortPairs(tmp, temp_bytes, dkeys, dvals, N,
                                    /*begin_bit=*/0, /*end_bit=*/32,
                                    /*stream=*/0);

    // Phase 2: stable partition by batch = bits [18,24) of the global index
    // (1 pass). Score rides along as the value.
    cub::DoubleBuffer<unsigned> pkeys(dvals.Current(), dvals.Alternate());
    cub::DoubleBuffer<unsigned> pvals(dkeys.Current(), dkeys.Alternate());
    temp_bytes = sizeof(g_temp);
    cub::DeviceRadixSort::SortPairs(tmp, temp_bytes, pkeys, pvals, N,
                                    /*begin_bit=*/18, /*end_bit=*/24,
                                    /*stream=*/0);

    decode_kernel<<<blocks, threads>>>(pkeys.Current(), pvals.Current(), off, out);
}